// round 1
// baseline (speedup 1.0000x reference)
#include <cuda_runtime.h>
#include <math.h>

#define N_CLS   3
#define N_YAW   2
#define NY      160
#define NX      160
#define N_ANCH  (N_YAW * NY * NX)   // 51200 anchors per class
#define N_BOX   32
#define CELLS_Y0 (NY * NX)           // 25600 (yaw-0 cells, for M_reg)

// output layout (concatenated flattened float32 in return order)
#define OFF_GCLS 0
#define SZ_GCLS  (N_CLS * N_ANCH)              // 153600
#define OFF_GREG (OFF_GCLS + SZ_GCLS)
#define SZ_GREG  (N_CLS * N_ANCH * 7)          // 1075200
#define OFF_MCLS (OFF_GREG + SZ_GREG)
#define SZ_MCLS  (N_ANCH)                      // 51200
#define OFF_MREG (OFF_MCLS + SZ_MCLS)
#define SZ_MREG  (N_CLS * CELLS_Y0)            // 76800

// scratch: full IoU matrix [cls][box][anchor] + per-(cls,box) highest IoU
__device__ float        g_iou[(size_t)N_CLS * N_BOX * N_ANCH];   // ~19.7 MB
__device__ unsigned int g_high[N_CLS * N_BOX];

__constant__ float c_low[3]  = {0.45f, 0.35f, 0.35f};
__constant__ float c_highth[3] = {0.60f, 0.50f, 0.50f};

struct V2 { float x, y; };

// Intersection area of two rotated rectangles via Sutherland-Hodgman.
// (cx,cy) center, (hw,hl) half width/length, (c,s) cos/sin yaw.
__device__ __forceinline__ float rect_inter_area(
    float cx1, float cy1, float hw1, float hl1, float c1, float s1,
    float cx2, float cy2, float hw2, float hl2, float c2, float s2)
{
    // initial polygon = rect2 corners (same corner order as reference)
    float ux2 = c2 * hw2, uy2 = s2 * hw2;
    float vx2 = -s2 * hl2, vy2 = c2 * hl2;
    V2 P[8], Q[8];
    P[0] = {cx2 + ux2 + vx2, cy2 + uy2 + vy2};
    P[1] = {cx2 + ux2 - vx2, cy2 + uy2 - vy2};
    P[2] = {cx2 - ux2 - vx2, cy2 - uy2 - vy2};
    P[3] = {cx2 - ux2 + vx2, cy2 - uy2 + vy2};
    int n = 4;

    // clip rect = rect1 corners (CW winding; interior: cross(edge, p-A) <= 0)
    float ux1 = c1 * hw1, uy1 = s1 * hw1;
    float vx1 = -s1 * hl1, vy1 = c1 * hl1;
    V2 CC[4];
    CC[0] = {cx1 + ux1 + vx1, cy1 + uy1 + vy1};
    CC[1] = {cx1 + ux1 - vx1, cy1 + uy1 - vy1};
    CC[2] = {cx1 - ux1 - vx1, cy1 - uy1 - vy1};
    CC[3] = {cx1 - ux1 + vx1, cy1 - uy1 + vy1};

    V2* src = P;
    V2* dst = Q;
    for (int e = 0; e < 4; e++) {
        V2 A = CC[e];
        V2 B = CC[(e + 1) & 3];
        float ex = B.x - A.x, ey = B.y - A.y;
        int m = 0;
        V2 pprev = src[n - 1];
        float dprev = ex * (pprev.y - A.y) - ey * (pprev.x - A.x);
        for (int i = 0; i < n; i++) {
            V2 p = src[i];
            float d = ex * (p.y - A.y) - ey * (p.x - A.x);
            bool inp = (d <= 0.0f), inprev = (dprev <= 0.0f);
            if (inprev != inp) {
                float t = dprev / (dprev - d);
                if (m < 8) { dst[m].x = pprev.x + t * (p.x - pprev.x);
                             dst[m].y = pprev.y + t * (p.y - pprev.y); m++; }
            }
            if (inp) { if (m < 8) dst[m++] = p; }
            dprev = d; pprev = p;
        }
        n = m;
        if (n == 0) return 0.0f;
        V2* tmp = src; src = dst; dst = tmp;
    }

    float ar = 0.0f;
    for (int i = 0; i < n; i++) {
        V2 p = src[i];
        V2 q = src[(i + 1 == n) ? 0 : (i + 1)];
        ar += p.x * q.y - q.x * p.y;
    }
    return 0.5f * fabsf(ar);
}

__global__ void init_high_kernel()
{
    int i = threadIdx.x;
    if (i < N_CLS * N_BOX) g_high[i] = 0u;
}

__global__ void iou_kernel(const float* __restrict__ boxes,
                           const float* __restrict__ anchors,
                           const int* __restrict__ cidx)
{
    const int cls = blockIdx.y;
    const int a = blockIdx.x * blockDim.x + threadIdx.x;

    // per-box precompute in shared: x, y, hw, hl, cos, sin, radius, area
    __shared__ float sb[8][N_BOX];
    __shared__ int   sv[N_BOX];
    if (threadIdx.x < N_BOX) {
        int b = threadIdx.x;
        float x = boxes[b * 7 + 0];
        float y = boxes[b * 7 + 1];
        float w = boxes[b * 7 + 3];
        float l = boxes[b * 7 + 4];
        float yaw = boxes[b * 7 + 6];
        sb[0][b] = x; sb[1][b] = y;
        sb[2][b] = 0.5f * w; sb[3][b] = 0.5f * l;
        sb[4][b] = cosf(yaw); sb[5][b] = sinf(yaw);
        sb[6][b] = 0.5f * sqrtf(w * w + l * l);
        sb[7][b] = w * l;
        sv[b] = (cidx[b] == cls) ? 1 : 0;
    }
    __syncthreads();
    if (a >= N_ANCH) return;

    const float* A = anchors + ((size_t)cls * N_ANCH + a) * 7;
    float ax = A[0], ay = A[1], aw = A[3], al = A[4], ayaw = A[6];
    float ac = cosf(ayaw), asn = sinf(ayaw);
    float ahw = 0.5f * aw, ahl = 0.5f * al;
    float arad = 0.5f * sqrtf(aw * aw + al * al);
    float aarea = aw * al;

    for (int b = 0; b < N_BOX; b++) {
        float iou = -1.0f;   // invalid-box mask value (matches reference)
        if (sv[b]) {
            iou = 0.0f;
            float dx = sb[0][b] - ax, dy = sb[1][b] - ay;
            float rr = sb[6][b] + arad;
            if (dx * dx + dy * dy <= rr * rr) {
                float inter = rect_inter_area(
                    sb[0][b], sb[1][b], sb[2][b], sb[3][b], sb[4][b], sb[5][b],
                    ax, ay, ahw, ahl, ac, asn);
                float uni = sb[7][b] + aarea - inter;
                iou = inter / fmaxf(uni, 1e-8f);
                iou = fminf(fmaxf(iou, 0.0f), 1.0f);
            }
            if (iou > 0.0f)
                atomicMax(&g_high[cls * N_BOX + b], __float_as_uint(iou));
        }
        g_iou[((size_t)(cls * N_BOX + b)) * N_ANCH + a] = iou;
    }
}

__global__ void combine_kernel(const float* __restrict__ boxes,
                               const float* __restrict__ anchors,
                               float* __restrict__ out)
{
    const int a = blockIdx.x * blockDim.x + threadIdx.x;
    if (a >= N_ANCH) return;

    int lab[N_CLS], midx[N_CLS];

    #pragma unroll
    for (int c = 0; c < N_CLS; c++) {
        float maxv = -2.0f;
        int idx = 0;
        bool lq = false;
        for (int b = 0; b < N_BOX; b++) {
            float v = g_iou[((size_t)(c * N_BOX + b)) * N_ANCH + a];
            if (v > maxv) { maxv = v; idx = b; }   // strict > = first argmax (jnp tie rule)
            // low-quality: valid (v>-1 implied by v>0), highest>0 implied by v>0,
            // bit-exact equality against atomicMax result
            if (v > 0.0f && __float_as_uint(v) == g_high[c * N_BOX + b]) lq = true;
        }
        int L = (maxv >= c_highth[c]) ? 1 : ((maxv >= c_low[c]) ? -1 : 0);
        if (lq) L = 1;
        lab[c] = L;
        midx[c] = idx;
    }

    // ambiguous: >1 class positive -> all -1
    int pos = (lab[0] == 1) + (lab[1] == 1) + (lab[2] == 1);
    if (pos > 1) { lab[0] = -1; lab[1] = -1; lab[2] = -1; }
    // negative & ~positive -> all 0 (evaluated on post-ambiguous labels)
    bool neg = (lab[0] == 0) || (lab[1] == 0) || (lab[2] == 0);
    int pos2 = (lab[0] == 1) + (lab[1] == 1) + (lab[2] == 1);
    bool positive = (pos2 == 1);
    if (neg && !positive) { lab[0] = 0; lab[1] = 0; lab[2] = 0; }
    // loss mask before -1 -> 0 replacement
    bool all_m1 = (lab[0] == -1) && (lab[1] == -1) && (lab[2] == -1);
    float loss_mask = all_m1 ? 0.0f : 1.0f;
    #pragma unroll
    for (int c = 0; c < N_CLS; c++)
        if (lab[c] == -1) lab[c] = 0;

    float* G_cls = out + OFF_GCLS;
    float* G_reg = out + OFF_GREG;
    float* M_cls = out + OFF_MCLS;
    float* M_reg = out + OFF_MREG;

    #pragma unroll
    for (int c = 0; c < N_CLS; c++) {
        G_cls[c * N_ANCH + a] = (float)lab[c];

        float vals[7] = {0.f, 0.f, 0.f, 0.f, 0.f, 0.f, 0.f};
        if (lab[c] == 1) {
            const float* B = boxes + midx[c] * 7;
            const float* A = anchors + ((size_t)c * N_ANCH + a) * 7;
            float nrm = sqrtf(A[3] * A[3] + A[4] * A[4]);
            vals[0] = (B[0] - A[0]) / nrm;
            vals[1] = (B[1] - A[1]) / nrm;
            vals[2] = (B[2] - A[2]) / A[5];
            vals[3] = logf(B[3] / A[3]);
            vals[4] = logf(B[4] / A[4]);
            vals[5] = logf(B[5] / A[5]);
            vals[6] = B[6] - A[6];
        }
        size_t base = ((size_t)c * N_ANCH + a) * 7;
        #pragma unroll
        for (int k = 0; k < 7; k++) G_reg[base + k] = vals[k];

        // M_reg = final labels at yaw slice 0 only (sum over yaws[:-1])
        if (a < CELLS_Y0) M_reg[c * CELLS_Y0 + a] = (float)lab[c];
    }
    M_cls[a] = loss_mask;
}

extern "C" void kernel_launch(void* const* d_in, const int* in_sizes, int n_in,
                              void* d_out, int out_size)
{
    const float* boxes = nullptr;
    const float* anchors = nullptr;
    const int* cidx = nullptr;
    for (int i = 0; i < n_in; i++) {
        if (in_sizes[i] == N_BOX * 7)            boxes = (const float*)d_in[i];
        else if (in_sizes[i] == N_CLS * N_ANCH * 7) anchors = (const float*)d_in[i];
        else if (in_sizes[i] == N_BOX)           cidx = (const int*)d_in[i];
    }
    float* out = (float*)d_out;

    init_high_kernel<<<1, 128>>>();

    dim3 gridA((N_ANCH + 255) / 256, N_CLS);
    iou_kernel<<<gridA, 256>>>(boxes, anchors, cidx);

    combine_kernel<<<(N_ANCH + 255) / 256, 256>>>(boxes, anchors, out);
}